// round 9
// baseline (speedup 1.0000x reference)
#include <cuda_runtime.h>
#include <stdint.h>

#define N_NODES 50000
#define N_EDGES 800000
#define D 64
#define BN_EPS 1e-5f
#define TILE_ROWS 64
#define GEMM_BLOCKS ((N_NODES + TILE_ROWS - 1) / TILE_ROWS)   // 782
#define SCAN_THREADS 1024
#define SCAN_CHUNK ((N_NODES + SCAN_THREADS - 1) / SCAN_THREADS)  // 49

// Scratch (static device globals — no allocations allowed)
__device__ float g_hpre[N_NODES * D];      // pre-BN GEMM1 output
__device__ float g_stats[2][2 * D];        // per-layer: [0:64) sums, [64:128) sumsq
__device__ int   g_deg   [N_NODES];
__device__ int   g_rowptr[N_NODES + 1];
__device__ int   g_cursor[N_NODES];
__device__ int   g_eidx  [N_EDGES];        // CSR: src node per slot, grouped by dst

// ---------------------------------------------------------------------------
// CSR build (once per launch; edge_index shared by both layers)
// ---------------------------------------------------------------------------
__global__ void k_zero_deg() {
    int i = blockIdx.x * blockDim.x + threadIdx.x;
    if (i < N_NODES) g_deg[i] = 0;
}

__global__ void k_hist(const int* __restrict__ dst) {
    int e = blockIdx.x * blockDim.x + threadIdx.x;
    if (e < N_EDGES) atomicAdd(&g_deg[dst[e]], 1);
}

// single-block exclusive prefix sum over g_deg -> g_rowptr / g_cursor,
// plus zero both layers' BN stats accumulators
__global__ __launch_bounds__(SCAN_THREADS) void k_scan() {
    __shared__ int part[SCAN_THREADS];
    int tid = threadIdx.x;
    int base = tid * SCAN_CHUNK;

    int s = 0;
    #pragma unroll
    for (int i = 0; i < SCAN_CHUNK; i++) {
        int idx = base + i;
        if (idx < N_NODES) s += g_deg[idx];
    }
    part[tid] = s;
    __syncthreads();

    // Hillis-Steele inclusive scan
    for (int off = 1; off < SCAN_THREADS; off <<= 1) {
        int v = 0;
        if (tid >= off) v = part[tid - off];
        __syncthreads();
        if (tid >= off) part[tid] += v;
        __syncthreads();
    }

    int run = (tid == 0) ? 0 : part[tid - 1];
    #pragma unroll
    for (int i = 0; i < SCAN_CHUNK; i++) {
        int idx = base + i;
        if (idx < N_NODES) {
            g_rowptr[idx] = run;
            g_cursor[idx] = run;
            run += g_deg[idx];
        }
    }
    if (tid == SCAN_THREADS - 1) g_rowptr[N_NODES] = N_EDGES;

    if (tid < 2 * D) { g_stats[0][tid] = 0.0f; g_stats[1][tid] = 0.0f; }
}

__global__ void k_fill(const int* __restrict__ src, const int* __restrict__ dst) {
    int e = blockIdx.x * blockDim.x + threadIdx.x;
    if (e < N_EDGES) {
        int pos = atomicAdd(&g_cursor[dst[e]], 1);
        g_eidx[pos] = src[e];
    }
}

// ---------------------------------------------------------------------------
// Fused: agg_i = x_i + sum_{j in CSR[i]} x_j  (in registers/smem),
// then hpre = agg @ W1 + b1, accumulating BN column sum / sumsq.
// Block = 256 threads = 8 warps; each warp gathers 8 rows (float2 per lane),
// then the block runs the 64x64 GEMM with 4x4 micro-tiles.
// ---------------------------------------------------------------------------
__global__ __launch_bounds__(256) void k_agg_gemm1(
    const float* __restrict__ x,
    const float* __restrict__ W1, const float* __restrict__ b1,
    float* __restrict__ stats)
{
    __shared__ float Ws[D * D];
    __shared__ float Xs[TILE_ROWS][D + 2];   // +2: keep float2 stores 8B-aligned
    __shared__ float s_sum[D], s_sq[D];

    int tid  = threadIdx.x;
    int lane = tid & 31;
    int warp = tid >> 5;
    int row0 = blockIdx.x * TILE_ROWS;
    int c2   = lane * 2;                     // this lane's 2 columns

    #pragma unroll
    for (int i = tid; i < D * D; i += 256) Ws[i] = W1[i];
    if (tid < D) { s_sum[tid] = 0.0f; s_sq[tid] = 0.0f; }

    // -------- gather phase --------
    #pragma unroll 1
    for (int r8 = 0; r8 < 8; r8++) {
        int rl  = warp * 8 + r8;
        int row = row0 + rl;
        float2 acc = make_float2(0.0f, 0.0f);
        if (row < N_NODES) {
            acc = *reinterpret_cast<const float2*>(x + (size_t)row * D + c2);
            int beg = g_rowptr[row];
            int end = g_rowptr[row + 1];
            int j = beg;
            for (; j + 2 <= end; j += 2) {          // 2 loads in flight
                int s0 = g_eidx[j];
                int s1 = g_eidx[j + 1];
                float2 v0 = *reinterpret_cast<const float2*>(x + (size_t)s0 * D + c2);
                float2 v1 = *reinterpret_cast<const float2*>(x + (size_t)s1 * D + c2);
                acc.x += v0.x + v1.x;
                acc.y += v0.y + v1.y;
            }
            if (j < end) {
                int s0 = g_eidx[j];
                float2 v0 = *reinterpret_cast<const float2*>(x + (size_t)s0 * D + c2);
                acc.x += v0.x;
                acc.y += v0.y;
            }
        }
        Xs[rl][c2]     = acc.x;
        Xs[rl][c2 + 1] = acc.y;
    }
    __syncthreads();

    // -------- GEMM phase --------
    int tx = tid & 15;   // col group (4 cols)
    int ty = tid >> 4;   // row group (4 rows)

    float4 acc[4];
    #pragma unroll
    for (int r = 0; r < 4; r++) acc[r] = make_float4(0.f, 0.f, 0.f, 0.f);

    #pragma unroll 8
    for (int k = 0; k < D; k++) {
        float4 w = *reinterpret_cast<const float4*>(&Ws[k * D + tx * 4]);
        #pragma unroll
        for (int r = 0; r < 4; r++) {
            float xv = Xs[ty * 4 + r][k];
            acc[r].x = fmaf(xv, w.x, acc[r].x);
            acc[r].y = fmaf(xv, w.y, acc[r].y);
            acc[r].z = fmaf(xv, w.z, acc[r].z);
            acc[r].w = fmaf(xv, w.w, acc[r].w);
        }
    }

    float4 bb = *reinterpret_cast<const float4*>(&b1[tx * 4]);
    float4 csum = make_float4(0.f, 0.f, 0.f, 0.f);
    float4 csq  = make_float4(0.f, 0.f, 0.f, 0.f);

    #pragma unroll
    for (int r = 0; r < 4; r++) {
        int row = row0 + ty * 4 + r;
        if (row < N_NODES) {
            float4 h;
            h.x = acc[r].x + bb.x;
            h.y = acc[r].y + bb.y;
            h.z = acc[r].z + bb.z;
            h.w = acc[r].w + bb.w;
            *reinterpret_cast<float4*>(&g_hpre[(size_t)row * D + tx * 4]) = h;
            csum.x += h.x;  csq.x = fmaf(h.x, h.x, csq.x);
            csum.y += h.y;  csq.y = fmaf(h.y, h.y, csq.y);
            csum.z += h.z;  csq.z = fmaf(h.z, h.z, csq.z);
            csum.w += h.w;  csq.w = fmaf(h.w, h.w, csq.w);
        }
    }
    atomicAdd(&s_sum[tx * 4 + 0], csum.x);
    atomicAdd(&s_sum[tx * 4 + 1], csum.y);
    atomicAdd(&s_sum[tx * 4 + 2], csum.z);
    atomicAdd(&s_sum[tx * 4 + 3], csum.w);
    atomicAdd(&s_sq [tx * 4 + 0], csq.x);
    atomicAdd(&s_sq [tx * 4 + 1], csq.y);
    atomicAdd(&s_sq [tx * 4 + 2], csq.z);
    atomicAdd(&s_sq [tx * 4 + 3], csq.w);
    __syncthreads();

    if (tid < D) {
        atomicAdd(&stats[tid],     s_sum[tid]);
        atomicAdd(&stats[D + tid], s_sq[tid]);
    }
}

// ---------------------------------------------------------------------------
// GEMM2: out = relu( relu(BN(g_hpre)) @ W2 + b2 )
// ---------------------------------------------------------------------------
__global__ __launch_bounds__(256) void k_gemm2(
    const float* __restrict__ W2, const float* __restrict__ b2,
    const float* __restrict__ gam, const float* __restrict__ beta,
    const float* __restrict__ stats,
    float* __restrict__ out)
{
    __shared__ float Ws[D * D];
    __shared__ float Xs[TILE_ROWS][D + 1];
    __shared__ float s_scale[D], s_shift[D];

    int tid = threadIdx.x;
    int row0 = blockIdx.x * TILE_ROWS;

    if (tid < D) {
        const float invN = 1.0f / (float)N_NODES;
        float mean = stats[tid] * invN;
        float var  = fmaf(-mean, mean, stats[D + tid] * invN);
        float sc   = gam[tid] * rsqrtf(var + BN_EPS);
        s_scale[tid] = sc;
        s_shift[tid] = beta[tid] - mean * sc;
    }
    #pragma unroll
    for (int i = tid; i < D * D; i += 256) Ws[i] = W2[i];
    __syncthreads();

    #pragma unroll
    for (int i = tid; i < TILE_ROWS * D; i += 256) {
        int r = i >> 6, c = i & 63;
        int row = row0 + r;
        float v = 0.0f;
        if (row < N_NODES) {
            v = fmaf(g_hpre[(size_t)row * D + c], s_scale[c], s_shift[c]);
            v = fmaxf(v, 0.0f);
        }
        Xs[r][c] = v;
    }
    __syncthreads();

    int tx = tid & 15;
    int ty = tid >> 4;

    float4 acc[4];
    #pragma unroll
    for (int r = 0; r < 4; r++) acc[r] = make_float4(0.f, 0.f, 0.f, 0.f);

    #pragma unroll 8
    for (int k = 0; k < D; k++) {
        float4 w = *reinterpret_cast<const float4*>(&Ws[k * D + tx * 4]);
        #pragma unroll
        for (int r = 0; r < 4; r++) {
            float xv = Xs[ty * 4 + r][k];
            acc[r].x = fmaf(xv, w.x, acc[r].x);
            acc[r].y = fmaf(xv, w.y, acc[r].y);
            acc[r].z = fmaf(xv, w.z, acc[r].z);
            acc[r].w = fmaf(xv, w.w, acc[r].w);
        }
    }

    float4 bb = *reinterpret_cast<const float4*>(&b2[tx * 4]);
    #pragma unroll
    for (int r = 0; r < 4; r++) {
        int row = row0 + ty * 4 + r;
        if (row < N_NODES) {
            float4 h;
            h.x = fmaxf(acc[r].x + bb.x, 0.0f);
            h.y = fmaxf(acc[r].y + bb.y, 0.0f);
            h.z = fmaxf(acc[r].z + bb.z, 0.0f);
            h.w = fmaxf(acc[r].w + bb.w, 0.0f);
            *reinterpret_cast<float4*>(&out[(size_t)row * D + tx * 4]) = h;
        }
    }
}

// ---------------------------------------------------------------------------
// launch
// ---------------------------------------------------------------------------
extern "C" void kernel_launch(void* const* d_in, const int* in_sizes, int n_in,
                              void* d_out, int out_size)
{
    const float* x    = (const float*)d_in[0];
    const int*   ei   = (const int*)d_in[1];      // int32 (JAX x64 disabled)
    const float* W1_0 = (const float*)d_in[2];
    const float* b1_0 = (const float*)d_in[3];
    const float* g_0  = (const float*)d_in[4];
    const float* be_0 = (const float*)d_in[5];
    const float* W2_0 = (const float*)d_in[6];
    const float* b2_0 = (const float*)d_in[7];
    const float* W1_1 = (const float*)d_in[8];
    const float* b1_1 = (const float*)d_in[9];
    const float* g_1  = (const float*)d_in[10];
    const float* be_1 = (const float*)d_in[11];
    const float* W2_1 = (const float*)d_in[12];
    const float* b2_1 = (const float*)d_in[13];

    const int* src = ei;              // edge_index[0] = message source
    const int* dst = ei + N_EDGES;    // edge_index[1] = aggregation target

    float* h1 = (float*)d_out;
    float* h2 = h1 + (size_t)N_NODES * D;

    float* st0; cudaGetSymbolAddress((void**)&st0, g_stats);
    float* st1 = st0 + 2 * D;

    // ---- CSR build (shared by both layers) ----
    k_zero_deg<<<(N_NODES + 255) / 256, 256>>>();
    k_hist    <<<(N_EDGES + 255) / 256, 256>>>(dst);
    k_scan    <<<1, SCAN_THREADS>>>();
    k_fill    <<<(N_EDGES + 255) / 256, 256>>>(src, dst);

    // ---- layer 0 ----
    k_agg_gemm1<<<GEMM_BLOCKS, 256>>>(x, W1_0, b1_0, st0);
    k_gemm2    <<<GEMM_BLOCKS, 256>>>(W2_0, b2_0, g_0, be_0, st0, h1);

    // ---- layer 1 ----
    k_agg_gemm1<<<GEMM_BLOCKS, 256>>>(h1, W1_1, b1_1, st1);
    k_gemm2    <<<GEMM_BLOCKS, 256>>>(W2_1, b2_1, g_1, be_1, st1, h2);
}

// round 10
// speedup vs baseline: 1.0506x; 1.0506x over previous
#include <cuda_runtime.h>
#include <stdint.h>

#define N_NODES 50000
#define N_EDGES 800000
#define D 64
#define BN_EPS 1e-5f
#define TILE_ROWS 64
#define GEMM_BLOCKS ((N_NODES + TILE_ROWS - 1) / TILE_ROWS)   // 782
#define SCAN_THREADS 1024
#define SCAN_CHUNK ((N_NODES + SCAN_THREADS - 1) / SCAN_THREADS)  // 49

// Scratch (static device globals — no allocations allowed)
__device__ float g_hpre[N_NODES * D];      // pre-BN GEMM1 output
__device__ float g_stats[2][2 * D];        // per-layer: [0:64) sums, [64:128) sumsq
__device__ int   g_deg   [N_NODES];
__device__ int   g_rowptr[N_NODES + 1];
__device__ int   g_cursor[N_NODES];
__device__ int   g_eidx  [N_EDGES];        // CSR: src node per slot, grouped by dst

// ---------------------------------------------------------------------------
// CSR build (once per launch; edge_index shared by both layers)
// ---------------------------------------------------------------------------
__global__ void k_zero_deg() {
    int i = blockIdx.x * blockDim.x + threadIdx.x;   // 12500 int4s exactly
    if (i < N_NODES / 4)
        reinterpret_cast<int4*>(g_deg)[i] = make_int4(0, 0, 0, 0);
}

__global__ void k_hist(const int* __restrict__ dst) {
    int e4 = blockIdx.x * blockDim.x + threadIdx.x;  // 200000 int4s exactly
    if (e4 < N_EDGES / 4) {
        int4 d = reinterpret_cast<const int4*>(dst)[e4];
        atomicAdd(&g_deg[d.x], 1);
        atomicAdd(&g_deg[d.y], 1);
        atomicAdd(&g_deg[d.z], 1);
        atomicAdd(&g_deg[d.w], 1);
    }
}

// single-block exclusive prefix sum over g_deg -> g_rowptr / g_cursor,
// plus zero both layers' BN stats accumulators
__global__ __launch_bounds__(SCAN_THREADS) void k_scan() {
    __shared__ int part[SCAN_THREADS];
    int tid = threadIdx.x;
    int base = tid * SCAN_CHUNK;

    int s = 0;
    #pragma unroll
    for (int i = 0; i < SCAN_CHUNK; i++) {
        int idx = base + i;
        if (idx < N_NODES) s += g_deg[idx];
    }
    part[tid] = s;
    __syncthreads();

    for (int off = 1; off < SCAN_THREADS; off <<= 1) {
        int v = 0;
        if (tid >= off) v = part[tid - off];
        __syncthreads();
        if (tid >= off) part[tid] += v;
        __syncthreads();
    }

    int run = (tid == 0) ? 0 : part[tid - 1];
    #pragma unroll
    for (int i = 0; i < SCAN_CHUNK; i++) {
        int idx = base + i;
        if (idx < N_NODES) {
            g_rowptr[idx] = run;
            g_cursor[idx] = run;
            run += g_deg[idx];
        }
    }
    if (tid == SCAN_THREADS - 1) g_rowptr[N_NODES] = N_EDGES;

    if (tid < 2 * D) { g_stats[0][tid] = 0.0f; g_stats[1][tid] = 0.0f; }
}

__global__ void k_fill(const int* __restrict__ src, const int* __restrict__ dst) {
    int e4 = blockIdx.x * blockDim.x + threadIdx.x;  // 200000 int4s exactly
    if (e4 < N_EDGES / 4) {
        int4 s = reinterpret_cast<const int4*>(src)[e4];
        int4 d = reinterpret_cast<const int4*>(dst)[e4];
        g_eidx[atomicAdd(&g_cursor[d.x], 1)] = s.x;
        g_eidx[atomicAdd(&g_cursor[d.y], 1)] = s.y;
        g_eidx[atomicAdd(&g_cursor[d.z], 1)] = s.z;
        g_eidx[atomicAdd(&g_cursor[d.w], 1)] = s.w;
    }
}

// ---------------------------------------------------------------------------
// Fused: agg_i = x_i + sum_{j in CSR[i]} x_j, then hpre = agg @ W1 + b1,
// accumulating BN column sum / sumsq.
// Gather: half-warp per row (16 lanes x float4); warp keeps 2 rows in flight;
// neighbor loop unrolled x4 -> 4 independent 16B loads per lane per iter.
// ---------------------------------------------------------------------------
__global__ __launch_bounds__(256) void k_agg_gemm1(
    const float* __restrict__ x,
    const float* __restrict__ W1, const float* __restrict__ b1,
    float* __restrict__ stats)
{
    __shared__ __align__(16) float Ws[D * D];
    __shared__ __align__(16) float Xs[TILE_ROWS][D + 4];
    __shared__ float s_sum[D], s_sq[D];

    int tid  = threadIdx.x;
    int lane = tid & 31;
    int warp = tid >> 5;
    int row0 = blockIdx.x * TILE_ROWS;
    int sub  = lane >> 4;            // which row of the warp's pair
    int q    = (lane & 15) << 2;     // float offset within row: 0,4,...,60

    #pragma unroll
    for (int i = tid; i < D * D / 4; i += 256)
        reinterpret_cast<float4*>(Ws)[i] =
            reinterpret_cast<const float4*>(W1)[i];
    if (tid < D) { s_sum[tid] = 0.0f; s_sq[tid] = 0.0f; }

    // -------- gather phase --------
    #pragma unroll 1
    for (int rp = 0; rp < 4; rp++) {
        int rl  = warp * 8 + rp * 2 + sub;
        int row = row0 + rl;
        float4 acc = make_float4(0.f, 0.f, 0.f, 0.f);
        if (row < N_NODES) {
            acc = *reinterpret_cast<const float4*>(x + (size_t)row * D + q);
            int beg = g_rowptr[row];
            int end = g_rowptr[row + 1];
            int j = beg;
            for (; j + 4 <= end; j += 4) {
                int s0 = g_eidx[j];
                int s1 = g_eidx[j + 1];
                int s2 = g_eidx[j + 2];
                int s3 = g_eidx[j + 3];
                float4 v0 = *reinterpret_cast<const float4*>(x + (size_t)s0 * D + q);
                float4 v1 = *reinterpret_cast<const float4*>(x + (size_t)s1 * D + q);
                float4 v2 = *reinterpret_cast<const float4*>(x + (size_t)s2 * D + q);
                float4 v3 = *reinterpret_cast<const float4*>(x + (size_t)s3 * D + q);
                acc.x += (v0.x + v1.x) + (v2.x + v3.x);
                acc.y += (v0.y + v1.y) + (v2.y + v3.y);
                acc.z += (v0.z + v1.z) + (v2.z + v3.z);
                acc.w += (v0.w + v1.w) + (v2.w + v3.w);
            }
            for (; j < end; j++) {
                int s0 = g_eidx[j];
                float4 v0 = *reinterpret_cast<const float4*>(x + (size_t)s0 * D + q);
                acc.x += v0.x; acc.y += v0.y; acc.z += v0.z; acc.w += v0.w;
            }
        }
        *reinterpret_cast<float4*>(&Xs[rl][q]) = acc;
    }
    __syncthreads();

    // -------- GEMM phase --------
    int tx = tid & 15;   // col group (4 cols)
    int ty = tid >> 4;   // row group (4 rows)

    float4 acc[4];
    #pragma unroll
    for (int r = 0; r < 4; r++) acc[r] = make_float4(0.f, 0.f, 0.f, 0.f);

    #pragma unroll 8
    for (int k = 0; k < D; k++) {
        float4 w = *reinterpret_cast<const float4*>(&Ws[k * D + tx * 4]);
        #pragma unroll
        for (int r = 0; r < 4; r++) {
            float xv = Xs[ty * 4 + r][k];
            acc[r].x = fmaf(xv, w.x, acc[r].x);
            acc[r].y = fmaf(xv, w.y, acc[r].y);
            acc[r].z = fmaf(xv, w.z, acc[r].z);
            acc[r].w = fmaf(xv, w.w, acc[r].w);
        }
    }

    float4 bb = *reinterpret_cast<const float4*>(&b1[tx * 4]);
    float4 csum = make_float4(0.f, 0.f, 0.f, 0.f);
    float4 csq  = make_float4(0.f, 0.f, 0.f, 0.f);

    #pragma unroll
    for (int r = 0; r < 4; r++) {
        int row = row0 + ty * 4 + r;
        if (row < N_NODES) {
            float4 h;
            h.x = acc[r].x + bb.x;
            h.y = acc[r].y + bb.y;
            h.z = acc[r].z + bb.z;
            h.w = acc[r].w + bb.w;
            *reinterpret_cast<float4*>(&g_hpre[(size_t)row * D + tx * 4]) = h;
            csum.x += h.x;  csq.x = fmaf(h.x, h.x, csq.x);
            csum.y += h.y;  csq.y = fmaf(h.y, h.y, csq.y);
            csum.z += h.z;  csq.z = fmaf(h.z, h.z, csq.z);
            csum.w += h.w;  csq.w = fmaf(h.w, h.w, csq.w);
        }
    }
    atomicAdd(&s_sum[tx * 4 + 0], csum.x);
    atomicAdd(&s_sum[tx * 4 + 1], csum.y);
    atomicAdd(&s_sum[tx * 4 + 2], csum.z);
    atomicAdd(&s_sum[tx * 4 + 3], csum.w);
    atomicAdd(&s_sq [tx * 4 + 0], csq.x);
    atomicAdd(&s_sq [tx * 4 + 1], csq.y);
    atomicAdd(&s_sq [tx * 4 + 2], csq.z);
    atomicAdd(&s_sq [tx * 4 + 3], csq.w);
    __syncthreads();

    if (tid < D) {
        atomicAdd(&stats[tid],     s_sum[tid]);
        atomicAdd(&stats[D + tid], s_sq[tid]);
    }
}

// ---------------------------------------------------------------------------
// GEMM2: out = relu( relu(BN(g_hpre)) @ W2 + b2 )
// ---------------------------------------------------------------------------
__global__ __launch_bounds__(256) void k_gemm2(
    const float* __restrict__ W2, const float* __restrict__ b2,
    const float* __restrict__ gam, const float* __restrict__ beta,
    const float* __restrict__ stats,
    float* __restrict__ out)
{
    __shared__ __align__(16) float Ws[D * D];
    __shared__ __align__(16) float Xs[TILE_ROWS][D + 4];
    __shared__ __align__(16) float s_scale[D];
    __shared__ __align__(16) float s_shift[D];

    int tid = threadIdx.x;
    int row0 = blockIdx.x * TILE_ROWS;

    if (tid < D) {
        const float invN = 1.0f / (float)N_NODES;
        float mean = stats[tid] * invN;
        float var  = fmaf(-mean, mean, stats[D + tid] * invN);
        float sc   = gam[tid] * rsqrtf(var + BN_EPS);
        s_scale[tid] = sc;
        s_shift[tid] = beta[tid] - mean * sc;
    }
    #pragma unroll
    for (int i = tid; i < D * D / 4; i += 256)
        reinterpret_cast<float4*>(Ws)[i] =
            reinterpret_cast<const float4*>(W2)[i];
    __syncthreads();

    // X-tile: vectorized load + BN + ReLU.  1024 float4s, 4 per thread.
    #pragma unroll
    for (int i = tid; i < TILE_ROWS * (D / 4); i += 256) {
        int r  = i >> 4;            // row in tile
        int c4 = (i & 15) << 2;     // float col
        int row = row0 + r;
        float4 v = make_float4(0.f, 0.f, 0.f, 0.f);
        if (row < N_NODES) {
            float4 hv = *reinterpret_cast<const float4*>(&g_hpre[(size_t)row * D + c4]);
            float4 sc = *reinterpret_cast<const float4*>(&s_scale[c4]);
            float4 sh = *reinterpret_cast<const float4*>(&s_shift[c4]);
            v.x = fmaxf(fmaf(hv.x, sc.x, sh.x), 0.0f);
            v.y = fmaxf(fmaf(hv.y, sc.y, sh.y), 0.0f);
            v.z = fmaxf(fmaf(hv.z, sc.z, sh.z), 0.0f);
            v.w = fmaxf(fmaf(hv.w, sc.w, sh.w), 0.0f);
        }
        *reinterpret_cast<float4*>(&Xs[r][c4]) = v;
    }
    __syncthreads();

    int tx = tid & 15;
    int ty = tid >> 4;

    float4 acc[4];
    #pragma unroll
    for (int r = 0; r < 4; r++) acc[r] = make_float4(0.f, 0.f, 0.f, 0.f);

    #pragma unroll 8
    for (int k = 0; k < D; k++) {
        float4 w = *reinterpret_cast<const float4*>(&Ws[k * D + tx * 4]);
        #pragma unroll
        for (int r = 0; r < 4; r++) {
            float xv = Xs[ty * 4 + r][k];
            acc[r].x = fmaf(xv, w.x, acc[r].x);
            acc[r].y = fmaf(xv, w.y, acc[r].y);
            acc[r].z = fmaf(xv, w.z, acc[r].z);
            acc[r].w = fmaf(xv, w.w, acc[r].w);
        }
    }

    float4 bb = *reinterpret_cast<const float4*>(&b2[tx * 4]);
    #pragma unroll
    for (int r = 0; r < 4; r++) {
        int row = row0 + ty * 4 + r;
        if (row < N_NODES) {
            float4 h;
            h.x = fmaxf(acc[r].x + bb.x, 0.0f);
            h.y = fmaxf(acc[r].y + bb.y, 0.0f);
            h.z = fmaxf(acc[r].z + bb.z, 0.0f);
            h.w = fmaxf(acc[r].w + bb.w, 0.0f);
            *reinterpret_cast<float4*>(&out[(size_t)row * D + tx * 4]) = h;
        }
    }
}

// ---------------------------------------------------------------------------
// launch
// ---------------------------------------------------------------------------
extern "C" void kernel_launch(void* const* d_in, const int* in_sizes, int n_in,
                              void* d_out, int out_size)
{
    const float* x    = (const float*)d_in[0];
    const int*   ei   = (const int*)d_in[1];      // int32 (JAX x64 disabled)
    const float* W1_0 = (const float*)d_in[2];
    const float* b1_0 = (const float*)d_in[3];
    const float* g_0  = (const float*)d_in[4];
    const float* be_0 = (const float*)d_in[5];
    const float* W2_0 = (const float*)d_in[6];
    const float* b2_0 = (const float*)d_in[7];
    const float* W1_1 = (const float*)d_in[8];
    const float* b1_1 = (const float*)d_in[9];
    const float* g_1  = (const float*)d_in[10];
    const float* be_1 = (const float*)d_in[11];
    const float* W2_1 = (const float*)d_in[12];
    const float* b2_1 = (const float*)d_in[13];

    const int* src = ei;              // edge_index[0] = message source
    const int* dst = ei + N_EDGES;    // edge_index[1] = aggregation target

    float* h1 = (float*)d_out;
    float* h2 = h1 + (size_t)N_NODES * D;

    float* st0; cudaGetSymbolAddress((void**)&st0, g_stats);
    float* st1 = st0 + 2 * D;

    // ---- CSR build (shared by both layers) ----
    k_zero_deg<<<(N_NODES / 4 + 255) / 256, 256>>>();
    k_hist    <<<(N_EDGES / 4 + 255) / 256, 256>>>(dst);
    k_scan    <<<1, SCAN_THREADS>>>();
    k_fill    <<<(N_EDGES / 4 + 255) / 256, 256>>>(src, dst);

    // ---- layer 0 ----
    k_agg_gemm1<<<GEMM_BLOCKS, 256>>>(x, W1_0, b1_0, st0);
    k_gemm2    <<<GEMM_BLOCKS, 256>>>(W2_0, b2_0, g_0, be_0, st0, h1);

    // ---- layer 1 ----
    k_agg_gemm1<<<GEMM_BLOCKS, 256>>>(h1, W1_1, b1_1, st1);
    k_gemm2    <<<GEMM_BLOCKS, 256>>>(W2_1, b2_1, g_1, be_1, st1, h2);
}

// round 12
// speedup vs baseline: 1.3950x; 1.3277x over previous
#include <cuda_runtime.h>
#include <stdint.h>

#define N_NODES 50000
#define N_EDGES 800000
#define D 64
#define BN_EPS 1e-5f
#define TILE_ROWS 64
#define XS_PITCH (D + 4)
#define GEMM_BLOCKS ((N_NODES + TILE_ROWS - 1) / TILE_ROWS)   // 782

// Scratch (static device globals — no allocations allowed)
__device__ float g_agg0[N_NODES * D];      // layer-0 neighbor sums
__device__ float g_agg1[N_NODES * D];      // layer-1 neighbor sums
__device__ float g_hpre[N_NODES * D];      // pre-BN GEMM1 output
__device__ float g_stats[2][2 * D];        // per-layer: [0:64) sums, [64:128) sumsq

// ---------------------------------------------------------------------------
// zero both agg buffers + both layers' BN stats accumulators (single launch,
// off the per-layer critical path)
// ---------------------------------------------------------------------------
__global__ void k_zero() {
    int i = blockIdx.x * blockDim.x + threadIdx.x;   // 2*800000 float4s exactly
    const int n4 = N_NODES * D / 4;
    float4 z = make_float4(0.f, 0.f, 0.f, 0.f);
    if (i < n4)          reinterpret_cast<float4*>(g_agg0)[i] = z;
    else if (i < 2 * n4) reinterpret_cast<float4*>(g_agg1)[i - n4] = z;
    if (blockIdx.x == 0 && threadIdx.x < 2 * 2 * D)
        (&g_stats[0][0])[threadIdx.x] = 0.0f;
}

// ---------------------------------------------------------------------------
// scatter: for each edge (s -> d): agg[d] += xin[s]
// 16 threads per edge; each thread moves one float4 via red.global.add.v4.
// This runs at the LTS throughput cap (~410 MB of L2 traffic per layer).
// ---------------------------------------------------------------------------
__global__ __launch_bounds__(256) void k_scatter(
    const float* __restrict__ xin,
    const int* __restrict__ src,
    const int* __restrict__ dst,
    float* __restrict__ agg)
{
    int tid = blockIdx.x * blockDim.x + threadIdx.x;
    int e = tid >> 4;                  // edge id
    if (e >= N_EDGES) return;
    int q = (tid & 15) << 2;           // float offset in row: 0,4,...,60

    int s = __ldg(&src[e]);            // 16 lanes broadcast (one L1 sector)
    int d = __ldg(&dst[e]);

    float4 v = *reinterpret_cast<const float4*>(xin + (size_t)s * D + q);
    size_t gaddr = __cvta_generic_to_global(agg + (size_t)d * D + q);
    asm volatile("red.global.add.v4.f32 [%0], {%1,%2,%3,%4};"
                 :: "l"(gaddr), "f"(v.x), "f"(v.y), "f"(v.z), "f"(v.w)
                 : "memory");
}

// ---------------------------------------------------------------------------
// GEMM1: hpre = (agg + x) @ W1 + b1, accumulating BN column sum / sumsq.
// k-blocked inner loop: 8 LDS.128 per 4 k-steps (vs 20 scalar-mixed before).
// ---------------------------------------------------------------------------
__global__ __launch_bounds__(256) void k_gemm1(
    const float* __restrict__ agg, const float* __restrict__ x,
    const float* __restrict__ W1, const float* __restrict__ b1,
    float* __restrict__ stats)
{
    __shared__ __align__(16) float Ws[D * D];
    __shared__ __align__(16) float Xs[TILE_ROWS][XS_PITCH];
    __shared__ float s_sum[D], s_sq[D];

    int tid = threadIdx.x;
    int row0 = blockIdx.x * TILE_ROWS;

    #pragma unroll
    for (int i = tid; i < D * D / 4; i += 256)
        reinterpret_cast<float4*>(Ws)[i] = reinterpret_cast<const float4*>(W1)[i];
    if (tid < D) { s_sum[tid] = 0.0f; s_sq[tid] = 0.0f; }

    // X-tile = agg + x (folds the GIN "+ x_i"); 1024 float4s, 4 per thread
    #pragma unroll
    for (int i = tid; i < TILE_ROWS * (D / 4); i += 256) {
        int r  = i >> 4;            // row in tile
        int c4 = (i & 15) << 2;     // float col
        int row = row0 + r;
        float4 v = make_float4(0.f, 0.f, 0.f, 0.f);
        if (row < N_NODES) {
            float4 a  = *reinterpret_cast<const float4*>(&agg[(size_t)row * D + c4]);
            float4 xv = *reinterpret_cast<const float4*>(&x  [(size_t)row * D + c4]);
            v.x = a.x + xv.x;  v.y = a.y + xv.y;
            v.z = a.z + xv.z;  v.w = a.w + xv.w;
        }
        *reinterpret_cast<float4*>(&Xs[r][c4]) = v;
    }
    __syncthreads();

    int tx = tid & 15;   // col group (4 cols)
    int ty = tid >> 4;   // row group (4 rows)

    float4 acc[4];
    #pragma unroll
    for (int r = 0; r < 4; r++) acc[r] = make_float4(0.f, 0.f, 0.f, 0.f);

    #pragma unroll 4
    for (int k = 0; k < D; k += 4) {
        float4 xr[4];
        #pragma unroll
        for (int r = 0; r < 4; r++)
            xr[r] = *reinterpret_cast<const float4*>(&Xs[ty * 4 + r][k]);
        #pragma unroll
        for (int i = 0; i < 4; i++) {
            float4 w = *reinterpret_cast<const float4*>(&Ws[(k + i) * D + tx * 4]);
            #pragma unroll
            for (int r = 0; r < 4; r++) {
                float xv = (i == 0) ? xr[r].x : (i == 1) ? xr[r].y
                         : (i == 2) ? xr[r].z : xr[r].w;
                acc[r].x = fmaf(xv, w.x, acc[r].x);
                acc[r].y = fmaf(xv, w.y, acc[r].y);
                acc[r].z = fmaf(xv, w.z, acc[r].z);
                acc[r].w = fmaf(xv, w.w, acc[r].w);
            }
        }
    }

    float4 bb = *reinterpret_cast<const float4*>(&b1[tx * 4]);
    float4 csum = make_float4(0.f, 0.f, 0.f, 0.f);
    float4 csq  = make_float4(0.f, 0.f, 0.f, 0.f);

    #pragma unroll
    for (int r = 0; r < 4; r++) {
        int row = row0 + ty * 4 + r;
        if (row < N_NODES) {
            float4 h;
            h.x = acc[r].x + bb.x;
            h.y = acc[r].y + bb.y;
            h.z = acc[r].z + bb.z;
            h.w = acc[r].w + bb.w;
            *reinterpret_cast<float4*>(&g_hpre[(size_t)row * D + tx * 4]) = h;
            csum.x += h.x;  csq.x = fmaf(h.x, h.x, csq.x);
            csum.y += h.y;  csq.y = fmaf(h.y, h.y, csq.y);
            csum.z += h.z;  csq.z = fmaf(h.z, h.z, csq.z);
            csum.w += h.w;  csq.w = fmaf(h.w, h.w, csq.w);
        }
    }
    atomicAdd(&s_sum[tx * 4 + 0], csum.x);
    atomicAdd(&s_sum[tx * 4 + 1], csum.y);
    atomicAdd(&s_sum[tx * 4 + 2], csum.z);
    atomicAdd(&s_sum[tx * 4 + 3], csum.w);
    atomicAdd(&s_sq [tx * 4 + 0], csq.x);
    atomicAdd(&s_sq [tx * 4 + 1], csq.y);
    atomicAdd(&s_sq [tx * 4 + 2], csq.z);
    atomicAdd(&s_sq [tx * 4 + 3], csq.w);
    __syncthreads();

    if (tid < D) {
        atomicAdd(&stats[tid],     s_sum[tid]);
        atomicAdd(&stats[D + tid], s_sq[tid]);
    }
}

// ---------------------------------------------------------------------------
// GEMM2: out = relu( relu(BN(g_hpre)) @ W2 + b2 )
// ---------------------------------------------------------------------------
__global__ __launch_bounds__(256) void k_gemm2(
    const float* __restrict__ W2, const float* __restrict__ b2,
    const float* __restrict__ gam, const float* __restrict__ beta,
    const float* __restrict__ stats,
    float* __restrict__ out)
{
    __shared__ __align__(16) float Ws[D * D];
    __shared__ __align__(16) float Xs[TILE_ROWS][XS_PITCH];
    __shared__ __align__(16) float s_scale[D];
    __shared__ __align__(16) float s_shift[D];

    int tid = threadIdx.x;
    int row0 = blockIdx.x * TILE_ROWS;

    if (tid < D) {
        const float invN = 1.0f / (float)N_NODES;
        float mean = stats[tid] * invN;
        float var  = fmaf(-mean, mean, stats[D + tid] * invN);
        float sc   = gam[tid] * rsqrtf(var + BN_EPS);
        s_scale[tid] = sc;
        s_shift[tid] = beta[tid] - mean * sc;
    }
    #pragma unroll
    for (int i = tid; i < D * D / 4; i += 256)
        reinterpret_cast<float4*>(Ws)[i] = reinterpret_cast<const float4*>(W2)[i];
    __syncthreads();

    #pragma unroll
    for (int i = tid; i < TILE_ROWS * (D / 4); i += 256) {
        int r  = i >> 4;
        int c4 = (i & 15) << 2;
        int row = row0 + r;
        float4 v = make_float4(0.f, 0.f, 0.f, 0.f);
        if (row < N_NODES) {
            float4 hv = *reinterpret_cast<const float4*>(&g_hpre[(size_t)row * D + c4]);
            float4 sc = *reinterpret_cast<const float4*>(&s_scale[c4]);
            float4 sh = *reinterpret_cast<const float4*>(&s_shift[c4]);
            v.x = fmaxf(fmaf(hv.x, sc.x, sh.x), 0.0f);
            v.y = fmaxf(fmaf(hv.y, sc.y, sh.y), 0.0f);
            v.z = fmaxf(fmaf(hv.z, sc.z, sh.z), 0.0f);
            v.w = fmaxf(fmaf(hv.w, sc.w, sh.w), 0.0f);
        }
        *reinterpret_cast<float4*>(&Xs[r][c4]) = v;
    }
    __syncthreads();

    int tx = tid & 15;
    int ty = tid >> 4;

    float4 acc[4];
    #pragma unroll
    for (int r = 0; r < 4; r++) acc[r] = make_float4(0.f, 0.f, 0.f, 0.f);

    #pragma unroll 4
    for (int k = 0; k < D; k += 4) {
        float4 xr[4];
        #pragma unroll
        for (int r = 0; r < 4; r++)
            xr[r] = *reinterpret_cast<const float4*>(&Xs[ty * 4 + r][k]);
        #pragma unroll
        for (int i = 0; i < 4; i++) {
            float4 w = *reinterpret_cast<const float4*>(&Ws[(k + i) * D + tx * 4]);
            #pragma unroll
            for (int r = 0; r < 4; r++) {
                float xv = (i == 0) ? xr[r].x : (i == 1) ? xr[r].y
                         : (i == 2) ? xr[r].z : xr[r].w;
                acc[r].x = fmaf(xv, w.x, acc[r].x);
                acc[r].y = fmaf(xv, w.y, acc[r].y);
                acc[r].z = fmaf(xv, w.z, acc[r].z);
                acc[r].w = fmaf(xv, w.w, acc[r].w);
            }
        }
    }

    float4 bb = *reinterpret_cast<const float4*>(&b2[tx * 4]);
    #pragma unroll
    for (int r = 0; r < 4; r++) {
        int row = row0 + ty * 4 + r;
        if (row < N_NODES) {
            float4 h;
            h.x = fmaxf(acc[r].x + bb.x, 0.0f);
            h.y = fmaxf(acc[r].y + bb.y, 0.0f);
            h.z = fmaxf(acc[r].z + bb.z, 0.0f);
            h.w = fmaxf(acc[r].w + bb.w, 0.0f);
            *reinterpret_cast<float4*>(&out[(size_t)row * D + tx * 4]) = h;
        }
    }
}

// ---------------------------------------------------------------------------
// launch
// ---------------------------------------------------------------------------
extern "C" void kernel_launch(void* const* d_in, const int* in_sizes, int n_in,
                              void* d_out, int out_size)
{
    const float* x    = (const float*)d_in[0];
    const int*   ei   = (const int*)d_in[1];      // int32 (JAX x64 disabled)
    const float* W1_0 = (const float*)d_in[2];
    const float* b1_0 = (const float*)d_in[3];
    const float* g_0  = (const float*)d_in[4];
    const float* be_0 = (const float*)d_in[5];
    const float* W2_0 = (const float*)d_in[6];
    const float* b2_0 = (const float*)d_in[7];
    const float* W1_1 = (const float*)d_in[8];
    const float* b1_1 = (const float*)d_in[9];
    const float* g_1  = (const float*)d_in[10];
    const float* be_1 = (const float*)d_in[11];
    const float* W2_1 = (const float*)d_in[12];
    const float* b2_1 = (const float*)d_in[13];

    const int* src = ei;              // edge_index[0] = message source
    const int* dst = ei + N_EDGES;    // edge_index[1] = aggregation target

    float* h1 = (float*)d_out;
    float* h2 = h1 + (size_t)N_NODES * D;

    float* a0;  cudaGetSymbolAddress((void**)&a0,  g_agg0);
    float* a1;  cudaGetSymbolAddress((void**)&a1,  g_agg1);
    float* st0; cudaGetSymbolAddress((void**)&st0, g_stats);
    float* st1 = st0 + 2 * D;

    // one upfront zero of both agg buffers + stats
    k_zero<<<(2 * N_NODES * D / 4 + 255) / 256, 256>>>();

    // ---- layer 0 ----
    k_scatter<<<(N_EDGES * 16 + 255) / 256, 256>>>(x, src, dst, a0);
    k_gemm1  <<<GEMM_BLOCKS, 256>>>(a0, x, W1_0, b1_0, st0);
    k_gemm2  <<<GEMM_BLOCKS, 256>>>(W2_0, b2_0, g_0, be_0, st0, h1);

    // ---- layer 1 ----
    k_scatter<<<(N_EDGES * 16 + 255) / 256, 256>>>(h1, src, dst, a1);
    k_gemm1  <<<GEMM_BLOCKS, 256>>>(a1, h1, W1_1, b1_1, st1);
    k_gemm2  <<<GEMM_BLOCKS, 256>>>(W2_1, b2_1, g_1, be_1, st1, h2);
}

// round 13
// speedup vs baseline: 1.5409x; 1.1046x over previous
#include <cuda_runtime.h>
#include <stdint.h>

#define N_NODES 50000
#define N_EDGES 800000
#define D 64
#define BN_EPS 1e-5f
#define TILE_ROWS 128
#define XS_PITCH (D + 4)
#define GEMM_BLOCKS ((N_NODES + TILE_ROWS - 1) / TILE_ROWS)   // 391

// Scratch (static device globals — no allocations allowed)
__device__ float g_agg0[N_NODES * D];      // layer-0 neighbor sums
__device__ float g_agg1[N_NODES * D];      // layer-1 neighbor sums
__device__ float g_hpre[N_NODES * D];      // pre-BN GEMM1 output
__device__ float g_stats[2][2 * D];        // per-layer: [0:64) sums, [64:128) sumsq

// ---------------------------------------------------------------------------
// zero both agg buffers + both layers' BN stats accumulators
// ---------------------------------------------------------------------------
__global__ void k_zero() {
    int i = blockIdx.x * blockDim.x + threadIdx.x;   // 2*800000 float4s exactly
    const int n4 = N_NODES * D / 4;
    float4 z = make_float4(0.f, 0.f, 0.f, 0.f);
    if (i < n4)          reinterpret_cast<float4*>(g_agg0)[i] = z;
    else if (i < 2 * n4) reinterpret_cast<float4*>(g_agg1)[i - n4] = z;
    if (blockIdx.x == 0 && threadIdx.x < 2 * 2 * D)
        (&g_stats[0][0])[threadIdx.x] = 0.0f;
}

// ---------------------------------------------------------------------------
// scatter: for each edge (s -> d): agg[d] += xin[s]
// 16 threads per edge, red.global.add.v4 — measured at ~90% of the LTS cap.
// ---------------------------------------------------------------------------
__global__ __launch_bounds__(256) void k_scatter(
    const float* __restrict__ xin,
    const int* __restrict__ src,
    const int* __restrict__ dst,
    float* __restrict__ agg)
{
    int tid = blockIdx.x * blockDim.x + threadIdx.x;
    int e = tid >> 4;                  // edge id
    if (e >= N_EDGES) return;
    int q = (tid & 15) << 2;           // float offset in row: 0,4,...,60

    int s = __ldg(&src[e]);            // 16 lanes broadcast (one L1 sector)
    int d = __ldg(&dst[e]);

    float4 v = *reinterpret_cast<const float4*>(xin + (size_t)s * D + q);
    size_t gaddr = __cvta_generic_to_global(agg + (size_t)d * D + q);
    asm volatile("red.global.add.v4.f32 [%0], {%1,%2,%3,%4};"
                 :: "l"(gaddr), "f"(v.x), "f"(v.y), "f"(v.z), "f"(v.w)
                 : "memory");
}

// ---------------------------------------------------------------------------
// Shared GEMM core: 128-row tile, 256 threads, 8 rows x 4 cols per thread.
// Row assignment strided by 16 (row = ty + 16*r) for bank-conflict-free
// Xs reads (68-word row pitch => 4-bank shift between warp's two rows).
// ---------------------------------------------------------------------------
__device__ __forceinline__ void gemm_core(
    const float (*Xs)[XS_PITCH], const float* Ws,
    int tx, int ty, float4 acc[8])
{
    #pragma unroll
    for (int r = 0; r < 8; r++) acc[r] = make_float4(0.f, 0.f, 0.f, 0.f);

    #pragma unroll 4
    for (int k = 0; k < D; k += 4) {
        float4 xr[8];
        #pragma unroll
        for (int r = 0; r < 8; r++)
            xr[r] = *reinterpret_cast<const float4*>(&Xs[ty + 16 * r][k]);
        #pragma unroll
        for (int i = 0; i < 4; i++) {
            float4 w = *reinterpret_cast<const float4*>(&Ws[(k + i) * D + tx * 4]);
            #pragma unroll
            for (int r = 0; r < 8; r++) {
                float xv = (i == 0) ? xr[r].x : (i == 1) ? xr[r].y
                         : (i == 2) ? xr[r].z : xr[r].w;
                acc[r].x = fmaf(xv, w.x, acc[r].x);
                acc[r].y = fmaf(xv, w.y, acc[r].y);
                acc[r].z = fmaf(xv, w.z, acc[r].z);
                acc[r].w = fmaf(xv, w.w, acc[r].w);
            }
        }
    }
}

// ---------------------------------------------------------------------------
// GEMM1: hpre = (agg + x) @ W1 + b1, accumulating BN column sum / sumsq.
// ---------------------------------------------------------------------------
__global__ __launch_bounds__(256) void k_gemm1(
    const float* __restrict__ agg, const float* __restrict__ x,
    const float* __restrict__ W1, const float* __restrict__ b1,
    float* __restrict__ stats)
{
    __shared__ __align__(16) float Ws[D * D];
    __shared__ __align__(16) float Xs[TILE_ROWS][XS_PITCH];
    __shared__ float s_sum[D], s_sq[D];

    int tid = threadIdx.x;
    int row0 = blockIdx.x * TILE_ROWS;

    #pragma unroll
    for (int i = tid; i < D * D / 4; i += 256)
        reinterpret_cast<float4*>(Ws)[i] = reinterpret_cast<const float4*>(W1)[i];
    if (tid < D) { s_sum[tid] = 0.0f; s_sq[tid] = 0.0f; }

    // X-tile = agg + x (folds the GIN "+ x_i"); 2048 float4s, 8 per thread
    #pragma unroll
    for (int i = tid; i < TILE_ROWS * (D / 4); i += 256) {
        int r  = i >> 4;            // row in tile
        int c4 = (i & 15) << 2;     // float col
        int row = row0 + r;
        float4 v = make_float4(0.f, 0.f, 0.f, 0.f);
        if (row < N_NODES) {
            float4 a  = *reinterpret_cast<const float4*>(&agg[(size_t)row * D + c4]);
            float4 xv = *reinterpret_cast<const float4*>(&x  [(size_t)row * D + c4]);
            v.x = a.x + xv.x;  v.y = a.y + xv.y;
            v.z = a.z + xv.z;  v.w = a.w + xv.w;
        }
        *reinterpret_cast<float4*>(&Xs[r][c4]) = v;
    }
    __syncthreads();

    int tx = tid & 15;   // col group (4 cols)
    int ty = tid >> 4;   // row base (rows ty, ty+16, ..., ty+112)

    float4 acc[8];
    gemm_core(Xs, Ws, tx, ty, acc);

    float4 bb = *reinterpret_cast<const float4*>(&b1[tx * 4]);
    float4 csum = make_float4(0.f, 0.f, 0.f, 0.f);
    float4 csq  = make_float4(0.f, 0.f, 0.f, 0.f);

    #pragma unroll
    for (int r = 0; r < 8; r++) {
        int row = row0 + ty + 16 * r;
        if (row < N_NODES) {
            float4 h;
            h.x = acc[r].x + bb.x;
            h.y = acc[r].y + bb.y;
            h.z = acc[r].z + bb.z;
            h.w = acc[r].w + bb.w;
            *reinterpret_cast<float4*>(&g_hpre[(size_t)row * D + tx * 4]) = h;
            csum.x += h.x;  csq.x = fmaf(h.x, h.x, csq.x);
            csum.y += h.y;  csq.y = fmaf(h.y, h.y, csq.y);
            csum.z += h.z;  csq.z = fmaf(h.z, h.z, csq.z);
            csum.w += h.w;  csq.w = fmaf(h.w, h.w, csq.w);
        }
    }
    atomicAdd(&s_sum[tx * 4 + 0], csum.x);
    atomicAdd(&s_sum[tx * 4 + 1], csum.y);
    atomicAdd(&s_sum[tx * 4 + 2], csum.z);
    atomicAdd(&s_sum[tx * 4 + 3], csum.w);
    atomicAdd(&s_sq [tx * 4 + 0], csq.x);
    atomicAdd(&s_sq [tx * 4 + 1], csq.y);
    atomicAdd(&s_sq [tx * 4 + 2], csq.z);
    atomicAdd(&s_sq [tx * 4 + 3], csq.w);
    __syncthreads();

    if (tid < D) {
        atomicAdd(&stats[tid],     s_sum[tid]);
        atomicAdd(&stats[D + tid], s_sq[tid]);
    }
}

// ---------------------------------------------------------------------------
// GEMM2: out = relu( relu(BN(g_hpre)) @ W2 + b2 )
// ---------------------------------------------------------------------------
__global__ __launch_bounds__(256) void k_gemm2(
    const float* __restrict__ W2, const float* __restrict__ b2,
    const float* __restrict__ gam, const float* __restrict__ beta,
    const float* __restrict__ stats,
    float* __restrict__ out)
{
    __shared__ __align__(16) float Ws[D * D];
    __shared__ __align__(16) float Xs[TILE_ROWS][XS_PITCH];
    __shared__ __align__(16) float s_scale[D];
    __shared__ __align__(16) float s_shift[D];

    int tid = threadIdx.x;
    int row0 = blockIdx.x * TILE_ROWS;

    if (tid < D) {
        const float invN = 1.0f / (float)N_NODES;
        float mean = stats[tid] * invN;
        float var  = fmaf(-mean, mean, stats[D + tid] * invN);
        float sc   = gam[tid] * rsqrtf(var + BN_EPS);
        s_scale[tid] = sc;
        s_shift[tid] = beta[tid] - mean * sc;
    }
    #pragma unroll
    for (int i = tid; i < D * D / 4; i += 256)
        reinterpret_cast<float4*>(Ws)[i] = reinterpret_cast<const float4*>(W2)[i];
    __syncthreads();

    #pragma unroll
    for (int i = tid; i < TILE_ROWS * (D / 4); i += 256) {
        int r  = i >> 4;
        int c4 = (i & 15) << 2;
        int row = row0 + r;
        float4 v = make_float4(0.f, 0.f, 0.f, 0.f);
        if (row < N_NODES) {
            float4 hv = *reinterpret_cast<const float4*>(&g_hpre[(size_t)row * D + c4]);
            float4 sc = *reinterpret_cast<const float4*>(&s_scale[c4]);
            float4 sh = *reinterpret_cast<const float4*>(&s_shift[c4]);
            v.x = fmaxf(fmaf(hv.x, sc.x, sh.x), 0.0f);
            v.y = fmaxf(fmaf(hv.y, sc.y, sh.y), 0.0f);
            v.z = fmaxf(fmaf(hv.z, sc.z, sh.z), 0.0f);
            v.w = fmaxf(fmaf(hv.w, sc.w, sh.w), 0.0f);
        }
        *reinterpret_cast<float4*>(&Xs[r][c4]) = v;
    }
    __syncthreads();

    int tx = tid & 15;
    int ty = tid >> 4;

    float4 acc[8];
    gemm_core(Xs, Ws, tx, ty, acc);

    float4 bb = *reinterpret_cast<const float4*>(&b2[tx * 4]);
    #pragma unroll
    for (int r = 0; r < 8; r++) {
        int row = row0 + ty + 16 * r;
        if (row < N_NODES) {
            float4 h;
            h.x = fmaxf(acc[r].x + bb.x, 0.0f);
            h.y = fmaxf(acc[r].y + bb.y, 0.0f);
            h.z = fmaxf(acc[r].z + bb.z, 0.0f);
            h.w = fmaxf(acc[r].w + bb.w, 0.0f);
            *reinterpret_cast<float4*>(&out[(size_t)row * D + tx * 4]) = h;
        }
    }
}

// ---------------------------------------------------------------------------
// launch
// ---------------------------------------------------------------------------
extern "C" void kernel_launch(void* const* d_in, const int* in_sizes, int n_in,
                              void* d_out, int out_size)
{
    const float* x    = (const float*)d_in[0];
    const int*   ei   = (const int*)d_in[1];      // int32 (JAX x64 disabled)
    const float* W1_0 = (const float*)d_in[2];
    const float* b1_0 = (const float*)d_in[3];
    const float* g_0  = (const float*)d_in[4];
    const float* be_0 = (const float*)d_in[5];
    const float* W2_0 = (const float*)d_in[6];
    const float* b2_0 = (const float*)d_in[7];
    const float* W1_1 = (const float*)d_in[8];
    const float* b1_1 = (const float*)d_in[9];
    const float* g_1  = (const float*)d_in[10];
    const float* be_1 = (const float*)d_in[11];
    const float* W2_1 = (const float*)d_in[12];
    const float* b2_1 = (const float*)d_in[13];

    const int* src = ei;              // edge_index[0] = message source
    const int* dst = ei + N_EDGES;    // edge_index[1] = aggregation target

    float* h1 = (float*)d_out;
    float* h2 = h1 + (size_t)N_NODES * D;

    float* a0;  cudaGetSymbolAddress((void**)&a0,  g_agg0);
    float* a1;  cudaGetSymbolAddress((void**)&a1,  g_agg1);
    float* st0; cudaGetSymbolAddress((void**)&st0, g_stats);
    float* st1 = st0 + 2 * D;

    // one upfront zero of both agg buffers + stats
    k_zero<<<(2 * N_NODES * D / 4 + 255) / 256, 256>>>();

    // ---- layer 0 ----
    k_scatter<<<(N_EDGES * 16 + 255) / 256, 256>>>(x, src, dst, a0);
    k_gemm1  <<<GEMM_BLOCKS, 256>>>(a0, x, W1_0, b1_0, st0);
    k_gemm2  <<<GEMM_BLOCKS, 256>>>(W2_0, b2_0, g_0, be_0, st0, h1);

    // ---- layer 1 ----
    k_scatter<<<(N_EDGES * 16 + 255) / 256, 256>>>(h1, src, dst, a1);
    k_gemm1  <<<GEMM_BLOCKS, 256>>>(a1, h1, W1_1, b1_1, st1);
    k_gemm2  <<<GEMM_BLOCKS, 256>>>(W2_1, b2_1, g_1, be_1, st1, h2);
}